// round 3
// baseline (speedup 1.0000x reference)
#include <cuda_runtime.h>

// ---------------------------------------------------------------------------
// Attention2D fused kernel (fp32 SIMT baseline, Round 2 resubmit — R1 bench
// died to container infra failure, no metrics were produced)
//
// Math (see reference):
//   Ws2  = Ws @ Ws                      (precomputed, tiny kernel)
//   q_   = q @ Ws                       (computed in-CTA, 2 rows/CTA)
//   k_   = k @ Ws                       (big GEMM #1)
//   v    = k @ Ws2                      (big GEMM #2, same A operand)
//   posf = relu(pos@Wp1+bp1)@Wp2+bp2
//   ain  = k_ - q_ + posf
//   a    = relu(ain@Wa1+ba1)@Wa2+ba2 ; mask==0 -> -1e9
//   p    = softmax over M (=16) per channel
//   y    = sum_m (v + posf) * p
//   x    = y @ Wo + bo
// ---------------------------------------------------------------------------

#define CDIM    256
#define HIDD    32
#define MTOK    16
#define TPC     2                    // tokens per CTA
#define RPC     (TPC * MTOK)         // 32 rows per CTA
#define SKS     264                  // smem row stride in floats (pad)
#define HS      36                   // hidden smem stride
#define NTOK    16384
#define NTHR    256

#define SMEM_FLOATS (RPC*SKS + RPC*SKS + RPC*HS + TPC*CDIM + TPC*SKS + TPC*SKS + RPC*4 + RPC)
#define SMEM_BYTES  (SMEM_FLOATS * 4)

__device__ float g_Ws2[CDIM * CDIM];

// ---------------------------------------------------------------------------
// Ws2 = Ws @ Ws   (256 CTAs x 256 threads; negligible cost)
// ---------------------------------------------------------------------------
__global__ void ws2_kernel(const float* __restrict__ Ws) {
    __shared__ float row[CDIM];
    const int r = blockIdx.x;
    const int c = threadIdx.x;
    row[c] = Ws[r * CDIM + c];
    __syncthreads();
    float acc = 0.f;
#pragma unroll 8
    for (int kk = 0; kk < CDIM; kk++)
        acc = fmaf(row[kk], __ldg(Ws + kk * CDIM + c), acc);
    g_Ws2[r * CDIM + c] = acc;
}

// ---------------------------------------------------------------------------
// Fused main kernel: one CTA = 2 tokens (32 k-rows)
// ---------------------------------------------------------------------------
__global__ __launch_bounds__(NTHR, 2)
void fused_kernel(const float* __restrict__ q,   const float* __restrict__ k,
                  const float* __restrict__ pos, const int*   __restrict__ mask,
                  const float* __restrict__ Ws,
                  const float* __restrict__ Wp1, const float* __restrict__ bp1,
                  const float* __restrict__ Wp2, const float* __restrict__ bp2,
                  const float* __restrict__ Wa1, const float* __restrict__ ba1,
                  const float* __restrict__ Wa2, const float* __restrict__ ba2,
                  const float* __restrict__ Wo,  const float* __restrict__ bo,
                  float* __restrict__ out)
{
    extern __shared__ float sm[];
    float* sm_k    = sm;                         // k tile; later: attn logits
    float* sm_vp   = sm_k  + RPC * SKS;          // v + posf
    float* sm_h    = sm_vp + RPC * SKS;          // pos hidden; later attn hidden
    float* sm_qr   = sm_h  + RPC * HS;           // raw q rows
    float* sm_qp   = sm_qr + TPC * CDIM;         // q_ = q@Ws rows
    float* sm_y    = sm_qp + TPC * SKS;          // per-token pooled output
    float* sm_pos  = sm_y  + TPC * SKS;          // pos tile
    int*   sm_mask = (int*)(sm_pos + RPC * 4);   // mask tile

    const int tid = threadIdx.x;
    const int cg  = tid & 63;        // column group: cols cg*4 .. cg*4+3
    const int rg  = tid >> 6;        // row group:    rows rg*8 .. rg*8+7
    const int tq  = blockIdx.x * TPC;      // first token of this CTA
    const int r0  = tq * MTOK;             // first k-row of this CTA

    // ---- stage tiles -------------------------------------------------------
    {
        const float* kp = k + (long)r0 * CDIM;
        for (int idx = tid; idx < RPC * 64; idx += NTHR) {
            const int m = idx >> 6, c4 = idx & 63;
            float4 v = __ldg((const float4*)(kp + m * CDIM) + c4);
            *(float4*)(sm_k + m * SKS + c4 * 4) = v;
        }
        if (tid < TPC * 64) {
            const int t = tid >> 6, c4 = tid & 63;
            float4 v = __ldg((const float4*)(q + (long)(tq + t) * CDIM) + c4);
            *(float4*)(sm_qr + t * CDIM + c4 * 4) = v;
        }
        if (tid < RPC) {
            float4 pv = __ldg((const float4*)pos + (r0 + tid));
            *(float4*)(sm_pos + tid * 4) = pv;
            sm_mask[tid] = __ldg(mask + r0 + tid);
        }
    }
    __syncthreads();

    // ---- big dual GEMM: s1 = k@Ws , s2 = k@Ws2 (per-thread 8x4 x2) --------
    float s1[8][4], s2[8][4];
#pragma unroll
    for (int i = 0; i < 8; i++)
#pragma unroll
        for (int j = 0; j < 4; j++) { s1[i][j] = 0.f; s2[i][j] = 0.f; }

    {
        const float* ap = sm_k + rg * 8 * SKS;
#pragma unroll 2
        for (int kk = 0; kk < CDIM; kk++) {
            const float4 w1 = __ldg((const float4*)(Ws     + kk * CDIM + cg * 4));
            const float4 w2 = *((const float4*)(g_Ws2      + kk * CDIM + cg * 4));
            float a[8];
#pragma unroll
            for (int i = 0; i < 8; i++) a[i] = ap[i * SKS + kk];
#pragma unroll
            for (int i = 0; i < 8; i++) {
                s1[i][0] = fmaf(a[i], w1.x, s1[i][0]);
                s1[i][1] = fmaf(a[i], w1.y, s1[i][1]);
                s1[i][2] = fmaf(a[i], w1.z, s1[i][2]);
                s1[i][3] = fmaf(a[i], w1.w, s1[i][3]);
                s2[i][0] = fmaf(a[i], w2.x, s2[i][0]);
                s2[i][1] = fmaf(a[i], w2.y, s2[i][1]);
                s2[i][2] = fmaf(a[i], w2.z, s2[i][2]);
                s2[i][3] = fmaf(a[i], w2.w, s2[i][3]);
            }
        }
    }
    __syncthreads();   // done reading sm_k (will be overwritten below)

    // ---- E0: q_ = q @ Ws (2 rows) ; E1: pos hidden h ----------------------
    {
#pragma unroll
        for (int rep = 0; rep < 2; rep++) {
            const int jid = tid + rep * 256;
            const int t = jid >> 8, c = jid & 255;
            const float* qr = sm_qr + t * CDIM;
            float acc = 0.f;
#pragma unroll 8
            for (int cc = 0; cc < CDIM; cc++)
                acc = fmaf(qr[cc], __ldg(Ws + cc * CDIM + c), acc);
            sm_qp[t * SKS + c] = acc;
        }
        const int m  = tid >> 3;
        const int jj = (tid & 7) * 4;
        const float p0 = sm_pos[m * 4 + 0], p1 = sm_pos[m * 4 + 1];
        const float p2 = sm_pos[m * 4 + 2], p3 = sm_pos[m * 4 + 3];
#pragma unroll
        for (int u = 0; u < 4; u++) {
            const int j = jj + u;
            float h = __ldg(bp1 + j);
            h = fmaf(p0, __ldg(Wp1 +  0 + j), h);
            h = fmaf(p1, __ldg(Wp1 + 32 + j), h);
            h = fmaf(p2, __ldg(Wp1 + 64 + j), h);
            h = fmaf(p3, __ldg(Wp1 + 96 + j), h);
            sm_h[m * HS + j] = fmaxf(h, 0.f);
        }
    }
    __syncthreads();

    // ---- E2: posf, attn_in -> sm_k, v+posf -> sm_vp -----------------------
    {
        const int tokl = rg >> 1;   // rows rg*8..rg*8+7 all belong to this local token
        const float qp0 = sm_qp[tokl * SKS + cg * 4 + 0];
        const float qp1 = sm_qp[tokl * SKS + cg * 4 + 1];
        const float qp2 = sm_qp[tokl * SKS + cg * 4 + 2];
        const float qp3 = sm_qp[tokl * SKS + cg * 4 + 3];
        const float4 b2 = __ldg((const float4*)(bp2 + cg * 4));
#pragma unroll
        for (int i = 0; i < 8; i++) {
            const int m = rg * 8 + i;
            float4 pf = b2;
#pragma unroll 4
            for (int j = 0; j < HIDD; j++) {
                const float hv = sm_h[m * HS + j];
                const float4 w = __ldg((const float4*)(Wp2 + j * CDIM + cg * 4));
                pf.x = fmaf(hv, w.x, pf.x);
                pf.y = fmaf(hv, w.y, pf.y);
                pf.z = fmaf(hv, w.z, pf.z);
                pf.w = fmaf(hv, w.w, pf.w);
            }
            float4 ai, vv;
            ai.x = s1[i][0] - qp0 + pf.x;  vv.x = s2[i][0] + pf.x;
            ai.y = s1[i][1] - qp1 + pf.y;  vv.y = s2[i][1] + pf.y;
            ai.z = s1[i][2] - qp2 + pf.z;  vv.z = s2[i][2] + pf.z;
            ai.w = s1[i][3] - qp3 + pf.w;  vv.w = s2[i][3] + pf.w;
            *(float4*)(sm_k  + m * SKS + cg * 4) = ai;
            *(float4*)(sm_vp + m * SKS + cg * 4) = vv;
        }
    }
    __syncthreads();

    // ---- E3: attn hidden h2 = relu(attn_in @ Wa1 + ba1) -> sm_h -----------
    {
        const int m = tid >> 3;
        const int j = (tid & 7) * 4;
        float4 acc = __ldg((const float4*)(ba1 + j));
        const float* as = sm_k + m * SKS;
#pragma unroll 4
        for (int c2 = 0; c2 < CDIM; c2++) {
            const float a = as[c2];
            const float4 w = __ldg((const float4*)(Wa1 + c2 * HIDD + j));
            acc.x = fmaf(a, w.x, acc.x);
            acc.y = fmaf(a, w.y, acc.y);
            acc.z = fmaf(a, w.z, acc.z);
            acc.w = fmaf(a, w.w, acc.w);
        }
        acc.x = fmaxf(acc.x, 0.f); acc.y = fmaxf(acc.y, 0.f);
        acc.z = fmaxf(acc.z, 0.f); acc.w = fmaxf(acc.w, 0.f);
        __syncthreads();          // everyone finished reading sm_h (E2) & sm_k
        *(float4*)(sm_h + m * HS + j) = acc;
    }
    __syncthreads();

    // ---- E4: logits = h2 @ Wa2 + ba2, masked -> sm_k ----------------------
    {
        const float4 b2 = __ldg((const float4*)(ba2 + cg * 4));
#pragma unroll
        for (int i = 0; i < 8; i++) {
            const int m = rg * 8 + i;
            float4 acc = b2;
#pragma unroll 4
            for (int j = 0; j < HIDD; j++) {
                const float hv = sm_h[m * HS + j];
                const float4 w = __ldg((const float4*)(Wa2 + j * CDIM + cg * 4));
                acc.x = fmaf(hv, w.x, acc.x);
                acc.y = fmaf(hv, w.y, acc.y);
                acc.z = fmaf(hv, w.z, acc.z);
                acc.w = fmaf(hv, w.w, acc.w);
            }
            if (sm_mask[m] == 0) { acc.x = -1e9f; acc.y = -1e9f; acc.z = -1e9f; acc.w = -1e9f; }
            *(float4*)(sm_k + m * SKS + cg * 4) = acc;
        }
    }
    __syncthreads();

    // ---- E5: per-channel softmax over M and weighted sum -> sm_y ----------
    {
#pragma unroll
        for (int rep = 0; rep < 2; rep++) {
            const int jid = tid + rep * 256;
            const int t = jid >> 8, c = jid & 255;
            const float* lp  = sm_k  + (t * MTOK) * SKS + c;
            const float* vpp = sm_vp + (t * MTOK) * SKS + c;
            float mx = -3.4e38f;
#pragma unroll
            for (int m = 0; m < MTOK; m++) mx = fmaxf(mx, lp[m * SKS]);
            float s = 0.f, acc = 0.f;
#pragma unroll
            for (int m = 0; m < MTOK; m++) {
                const float e = __expf(lp[m * SKS] - mx);
                s += e;
                acc = fmaf(e, vpp[m * SKS], acc);
            }
            sm_y[t * SKS + c] = acc / s;
        }
    }
    __syncthreads();

    // ---- E6: x = y @ Wo + bo ----------------------------------------------
    {
#pragma unroll
        for (int rep = 0; rep < 2; rep++) {
            const int jid = tid + rep * 256;
            const int t = jid >> 8, c = jid & 255;
            const float* yy = sm_y + t * SKS;
            float acc = __ldg(bo + c);
#pragma unroll 8
            for (int cc = 0; cc < CDIM; cc++)
                acc = fmaf(yy[cc], __ldg(Wo + cc * CDIM + c), acc);
            out[(long)(tq + t) * CDIM + c] = acc;
        }
    }
}

// ---------------------------------------------------------------------------
extern "C" void kernel_launch(void* const* d_in, const int* in_sizes, int n_in,
                              void* d_out, int out_size) {
    const float* q   = (const float*)d_in[0];
    const float* k   = (const float*)d_in[1];
    const float* pos = (const float*)d_in[2];
    const int*   mask= (const int*)  d_in[3];
    const float* Ws  = (const float*)d_in[4];
    const float* Wp1 = (const float*)d_in[5];
    const float* bp1 = (const float*)d_in[6];
    const float* Wp2 = (const float*)d_in[7];
    const float* bp2 = (const float*)d_in[8];
    const float* Wa1 = (const float*)d_in[9];
    const float* ba1 = (const float*)d_in[10];
    const float* Wa2 = (const float*)d_in[11];
    const float* ba2 = (const float*)d_in[12];
    const float* Wo  = (const float*)d_in[13];
    const float* bo  = (const float*)d_in[14];
    float* out = (float*)d_out;

    cudaFuncSetAttribute(fused_kernel,
                         cudaFuncAttributeMaxDynamicSharedMemorySize, SMEM_BYTES);

    ws2_kernel<<<CDIM, CDIM>>>(Ws);
    fused_kernel<<<NTOK / TPC, NTHR, SMEM_BYTES>>>(
        q, k, pos, mask, Ws, Wp1, bp1, Wp2, bp2,
        Wa1, ba1, Wa2, ba2, Wo, bo, out);
}

// round 5
// speedup vs baseline: 1.1513x; 1.1513x over previous
#include <cuda_runtime.h>
#include <cstdint>

// ---------------------------------------------------------------------------
// Attention2D fused kernel — Round 5: dual GEMM on tensor cores (3xTF32).
// R4 resubmit after infra failure, with register-pressure fix: B fragments
// preloaded per k-step (16 regs), A fragments loaded just-in-time per m-tile
// (8 regs live) so peak live set stays well under the 128-reg cap.
// ---------------------------------------------------------------------------

#define CDIM    256
#define HIDD    32
#define MTOK    16
#define TPC     4                    // tokens per CTA
#define RPC     (TPC * MTOK)         // 64 rows per CTA
#define SKS     260                  // smem row stride (conflict-free frags)
#define HS      36
#define NTOK    16384
#define NTHR    512
#define NKSTEP  (CDIM / 8)           // 32 k-steps of 8

#define SMEM_FLOATS (2*RPC*SKS + RPC*HS + TPC*CDIM + TPC*SKS + TPC*SKS + RPC*4 + RPC)
#define SMEM_BYTES  (SMEM_FLOATS * 4)

__device__ float g_Ws2[CDIM * CDIM];

__device__ __forceinline__ uint32_t f2tf32(float x) {
    uint32_t r;
    asm("cvt.rna.tf32.f32 %0, %1;" : "=r"(r) : "f"(x));
    return r;
}

__device__ __forceinline__ void mma8(float* d, const uint32_t* a,
                                     uint32_t b0, uint32_t b1) {
    asm volatile(
        "mma.sync.aligned.m16n8k8.row.col.f32.tf32.tf32.f32 "
        "{%0,%1,%2,%3}, {%4,%5,%6,%7}, {%8,%9}, {%0,%1,%2,%3};"
        : "+f"(d[0]), "+f"(d[1]), "+f"(d[2]), "+f"(d[3])
        : "r"(a[0]), "r"(a[1]), "r"(a[2]), "r"(a[3]), "r"(b0), "r"(b1));
}

// ---------------------------------------------------------------------------
__global__ void ws2_kernel(const float* __restrict__ Ws) {
    __shared__ float row[CDIM];
    const int r = blockIdx.x, c = threadIdx.x;
    row[c] = Ws[r * CDIM + c];
    __syncthreads();
    float acc = 0.f;
#pragma unroll 8
    for (int kk = 0; kk < CDIM; kk++)
        acc = fmaf(row[kk], __ldg(Ws + kk * CDIM + c), acc);
    g_Ws2[r * CDIM + c] = acc;
}

// ---------------------------------------------------------------------------
__global__ __launch_bounds__(NTHR, 1)
void fused_kernel(const float* __restrict__ q,   const float* __restrict__ k,
                  const float* __restrict__ pos, const int*   __restrict__ mask,
                  const float* __restrict__ Ws,
                  const float* __restrict__ Wp1, const float* __restrict__ bp1,
                  const float* __restrict__ Wp2, const float* __restrict__ bp2,
                  const float* __restrict__ Wa1, const float* __restrict__ ba1,
                  const float* __restrict__ Wa2, const float* __restrict__ ba2,
                  const float* __restrict__ Wo,  const float* __restrict__ bo,
                  float* __restrict__ out)
{
    extern __shared__ float sm[];
    float* sm_a    = sm;                         // A_hi -> s1 -> ai -> logits
    float* sm_b    = sm_a  + RPC * SKS;          // A_lo -> s2 -> vv
    float* sm_h    = sm_b  + RPC * SKS;          // pos hidden, then attn hidden
    float* sm_qr   = sm_h  + RPC * HS;           // raw q rows
    float* sm_qp   = sm_qr + TPC * CDIM;         // q_ rows
    float* sm_y    = sm_qp + TPC * SKS;          // pooled output
    float* sm_pos  = sm_y  + TPC * SKS;
    int*   sm_mask = (int*)(sm_pos + RPC * 4);

    const int tid = threadIdx.x;
    const int tq  = blockIdx.x * TPC;
    const int r0g = tq * MTOK;

    // ---- stage: k rows split into tf32 hi/lo; q, pos, mask ----------------
    {
        const float* kp = k + (long)r0g * CDIM;
        for (int idx = tid; idx < RPC * 64; idx += NTHR) {
            const int m = idx >> 6, c4 = idx & 63;
            float4 v = __ldg((const float4*)(kp + m * CDIM) + c4);
            float4 hi, lo;
            hi.x = __uint_as_float(f2tf32(v.x)); lo.x = __uint_as_float(f2tf32(v.x - hi.x));
            hi.y = __uint_as_float(f2tf32(v.y)); lo.y = __uint_as_float(f2tf32(v.y - hi.y));
            hi.z = __uint_as_float(f2tf32(v.z)); lo.z = __uint_as_float(f2tf32(v.z - hi.z));
            hi.w = __uint_as_float(f2tf32(v.w)); lo.w = __uint_as_float(f2tf32(v.w - hi.w));
            *(float4*)(sm_a + m * SKS + c4 * 4) = hi;
            *(float4*)(sm_b + m * SKS + c4 * 4) = lo;
        }
        if (tid < TPC * 64) {
            const int t = tid >> 6, c4 = tid & 63;
            float4 v = __ldg((const float4*)(q + (long)(tq + t) * CDIM) + c4);
            *(float4*)(sm_qr + t * CDIM + c4 * 4) = v;
        }
        if (tid < RPC) {
            float4 pv = __ldg((const float4*)pos + (r0g + tid));
            *(float4*)(sm_pos + tid * 4) = pv;
            sm_mask[tid] = __ldg(mask + r0g + tid);
        }
    }
    __syncthreads();

    // ---- dual GEMM via mma.sync tf32 (3xTF32) -----------------------------
    // 16 warps: w<8 -> s1 = k@Ws, cols (w&7)*32..+31 ; w>=8 -> s2 = k@Ws2
    {
        const int wid  = tid >> 5, lane = tid & 31;
        const int gid  = lane >> 2, tig = lane & 3;
        const float* Bmat = (wid < 8) ? Ws : g_Ws2;
        const int ncb = (wid & 7) * 32;

        float d[4][4][4];
#pragma unroll
        for (int mi = 0; mi < 4; mi++)
#pragma unroll
            for (int ni = 0; ni < 4; ni++)
#pragma unroll
                for (int c = 0; c < 4; c++) d[mi][ni][c] = 0.f;

        for (int ks = 0; ks < NKSTEP; ks++) {
            const int k0 = ks * 8;
            // preload 4 B column fragments (reused by all 4 m-tiles)
            uint32_t bh0[4], bh1[4], bl0[4], bl1[4];
#pragma unroll
            for (int ni = 0; ni < 4; ni++) {
                const int bc = ncb + ni * 8 + gid;
                const float b0f = __ldg(Bmat + (k0 + tig)     * CDIM + bc);
                const float b1f = __ldg(Bmat + (k0 + tig + 4) * CDIM + bc);
                bh0[ni] = f2tf32(b0f);
                bh1[ni] = f2tf32(b1f);
                bl0[ni] = f2tf32(b0f - __uint_as_float(bh0[ni]));
                bl1[ni] = f2tf32(b1f - __uint_as_float(bh1[ni]));
            }
#pragma unroll
            for (int mi = 0; mi < 4; mi++) {
                const int ra = (mi * 16 + gid) * SKS + k0 + tig;
                const int rb = ra + 8 * SKS;
                uint32_t ah[4], al[4];
                ah[0] = __float_as_uint(sm_a[ra]);
                ah[1] = __float_as_uint(sm_a[rb]);
                ah[2] = __float_as_uint(sm_a[ra + 4]);
                ah[3] = __float_as_uint(sm_a[rb + 4]);
                al[0] = __float_as_uint(sm_b[ra]);
                al[1] = __float_as_uint(sm_b[rb]);
                al[2] = __float_as_uint(sm_b[ra + 4]);
                al[3] = __float_as_uint(sm_b[rb + 4]);
#pragma unroll
                for (int ni = 0; ni < 4; ni++) {
                    mma8(d[mi][ni], ah, bh0[ni], bh1[ni]);   // hi*hi
                    mma8(d[mi][ni], al, bh0[ni], bh1[ni]);   // lo*hi
                    mma8(d[mi][ni], ah, bl0[ni], bl1[ni]);   // hi*lo
                }
            }
        }
        __syncthreads();                 // all warps done reading A
        float* dst = (wid < 8) ? sm_a : sm_b;
#pragma unroll
        for (int mi = 0; mi < 4; mi++)
#pragma unroll
            for (int ni = 0; ni < 4; ni++) {
                const int r0 = mi * 16 + gid;
                const int c0 = ncb + ni * 8 + 2 * tig;
                *(float2*)&dst[r0 * SKS + c0]       = make_float2(d[mi][ni][0], d[mi][ni][1]);
                *(float2*)&dst[(r0 + 8) * SKS + c0] = make_float2(d[mi][ni][2], d[mi][ni][3]);
            }
    }
    __syncthreads();

    const int cg = tid & 63;
    const int rg = tid >> 6;

    // ---- E0: q_ = q @ Ws (fp32) ; E1: pos hidden --------------------------
    {
#pragma unroll
        for (int rep = 0; rep < 2; rep++) {
            const int jid = tid + rep * NTHR;
            const int t = jid >> 8, c = jid & 255;
            const float* qr = sm_qr + t * CDIM;
            float acc = 0.f;
#pragma unroll 8
            for (int cc = 0; cc < CDIM; cc++)
                acc = fmaf(qr[cc], __ldg(Ws + cc * CDIM + c), acc);
            sm_qp[t * SKS + c] = acc;
        }
        const int m  = tid >> 3;
        const int jj = (tid & 7) * 4;
        const float p0 = sm_pos[m * 4 + 0], p1 = sm_pos[m * 4 + 1];
        const float p2 = sm_pos[m * 4 + 2], p3 = sm_pos[m * 4 + 3];
#pragma unroll
        for (int u = 0; u < 4; u++) {
            const int j = jj + u;
            float h = __ldg(bp1 + j);
            h = fmaf(p0, __ldg(Wp1 +  0 + j), h);
            h = fmaf(p1, __ldg(Wp1 + 32 + j), h);
            h = fmaf(p2, __ldg(Wp1 + 64 + j), h);
            h = fmaf(p3, __ldg(Wp1 + 96 + j), h);
            sm_h[m * HS + j] = fmaxf(h, 0.f);
        }
    }
    __syncthreads();

    // ---- E2: posf ; ai = s1 - q_ + posf -> sm_a ; vv = s2 + posf -> sm_b --
    {
        const int tokl = rg >> 1;
        const float qp0 = sm_qp[tokl * SKS + cg * 4 + 0];
        const float qp1 = sm_qp[tokl * SKS + cg * 4 + 1];
        const float qp2 = sm_qp[tokl * SKS + cg * 4 + 2];
        const float qp3 = sm_qp[tokl * SKS + cg * 4 + 3];
        const float4 b2 = __ldg((const float4*)(bp2 + cg * 4));
#pragma unroll
        for (int i = 0; i < 8; i++) {
            const int m = rg * 8 + i;
            float4 pf = b2;
#pragma unroll 4
            for (int j = 0; j < HIDD; j++) {
                const float hv = sm_h[m * HS + j];
                const float4 w = __ldg((const float4*)(Wp2 + j * CDIM + cg * 4));
                pf.x = fmaf(hv, w.x, pf.x);
                pf.y = fmaf(hv, w.y, pf.y);
                pf.z = fmaf(hv, w.z, pf.z);
                pf.w = fmaf(hv, w.w, pf.w);
            }
            float4 s1v = *(const float4*)(sm_a + m * SKS + cg * 4);
            float4 s2v = *(const float4*)(sm_b + m * SKS + cg * 4);
            float4 ai, vv;
            ai.x = s1v.x - qp0 + pf.x;  vv.x = s2v.x + pf.x;
            ai.y = s1v.y - qp1 + pf.y;  vv.y = s2v.y + pf.y;
            ai.z = s1v.z - qp2 + pf.z;  vv.z = s2v.z + pf.z;
            ai.w = s1v.w - qp3 + pf.w;  vv.w = s2v.w + pf.w;
            *(float4*)(sm_a + m * SKS + cg * 4) = ai;
            *(float4*)(sm_b + m * SKS + cg * 4) = vv;
        }
    }
    __syncthreads();

    // ---- E3: h2 = relu(ai @ Wa1 + ba1) ------------------------------------
    {
        const int m = tid >> 3;
        const int j = (tid & 7) * 4;
        float4 acc = __ldg((const float4*)(ba1 + j));
        const float* as = sm_a + m * SKS;
#pragma unroll 4
        for (int c2 = 0; c2 < CDIM; c2++) {
            const float a = as[c2];
            const float4 w = __ldg((const float4*)(Wa1 + c2 * HIDD + j));
            acc.x = fmaf(a, w.x, acc.x);
            acc.y = fmaf(a, w.y, acc.y);
            acc.z = fmaf(a, w.z, acc.z);
            acc.w = fmaf(a, w.w, acc.w);
        }
        acc.x = fmaxf(acc.x, 0.f); acc.y = fmaxf(acc.y, 0.f);
        acc.z = fmaxf(acc.z, 0.f); acc.w = fmaxf(acc.w, 0.f);
        __syncthreads();          // all reads of sm_h (E2) done
        *(float4*)(sm_h + m * HS + j) = acc;
    }
    __syncthreads();

    // ---- E4: logits = h2 @ Wa2 + ba2, masked -> sm_a ----------------------
    {
        const float4 b2 = __ldg((const float4*)(ba2 + cg * 4));
#pragma unroll
        for (int i = 0; i < 8; i++) {
            const int m = rg * 8 + i;
            float4 acc = b2;
#pragma unroll 4
            for (int j = 0; j < HIDD; j++) {
                const float hv = sm_h[m * HS + j];
                const float4 w = __ldg((const float4*)(Wa2 + j * CDIM + cg * 4));
                acc.x = fmaf(hv, w.x, acc.x);
                acc.y = fmaf(hv, w.y, acc.y);
                acc.z = fmaf(hv, w.z, acc.z);
                acc.w = fmaf(hv, w.w, acc.w);
            }
            if (sm_mask[m] == 0) { acc.x = -1e9f; acc.y = -1e9f; acc.z = -1e9f; acc.w = -1e9f; }
            *(float4*)(sm_a + m * SKS + cg * 4) = acc;
        }
    }
    __syncthreads();

    // ---- E5: per-channel softmax over M, weighted sum -> sm_y -------------
    {
#pragma unroll
        for (int rep = 0; rep < 2; rep++) {
            const int jid = tid + rep * NTHR;
            const int t = jid >> 8, c = jid & 255;
            const float* lp  = sm_a + (t * MTOK) * SKS + c;
            const float* vpp = sm_b + (t * MTOK) * SKS + c;
            float mx = -3.4e38f;
#pragma unroll
            for (int m = 0; m < MTOK; m++) mx = fmaxf(mx, lp[m * SKS]);
            float s = 0.f, acc = 0.f;
#pragma unroll
            for (int m = 0; m < MTOK; m++) {
                const float e = __expf(lp[m * SKS] - mx);
                s += e;
                acc = fmaf(e, vpp[m * SKS], acc);
            }
            sm_y[t * SKS + c] = acc / s;
        }
    }
    __syncthreads();

    // ---- E6: x = y @ Wo + bo ----------------------------------------------
    {
#pragma unroll
        for (int rep = 0; rep < 2; rep++) {
            const int jid = tid + rep * NTHR;
            const int t = jid >> 8, c = jid & 255;
            const float* yy = sm_y + t * SKS;
            float acc = __ldg(bo + c);
#pragma unroll 8
            for (int cc = 0; cc < CDIM; cc++)
                acc = fmaf(yy[cc], __ldg(Wo + cc * CDIM + c), acc);
            out[(long)(tq + t) * CDIM + c] = acc;
        }
    }
}

// ---------------------------------------------------------------------------
extern "C" void kernel_launch(void* const* d_in, const int* in_sizes, int n_in,
                              void* d_out, int out_size) {
    const float* q   = (const float*)d_in[0];
    const float* k   = (const float*)d_in[1];
    const float* pos = (const float*)d_in[2];
    const int*   mask= (const int*)  d_in[3];
    const float* Ws  = (const float*)d_in[4];
    const float* Wp1 = (const float*)d_in[5];
    const float* bp1 = (const float*)d_in[6];
    const float* Wp2 = (const float*)d_in[7];
    const float* bp2 = (const float*)d_in[8];
    const float* Wa1 = (const float*)d_in[9];
    const float* ba1 = (const float*)d_in[10];
    const float* Wa2 = (const float*)d_in[11];
    const float* ba2 = (const float*)d_in[12];
    const float* Wo  = (const float*)d_in[13];
    const float* bo  = (const float*)d_in[14];
    float* out = (float*)d_out;

    cudaFuncSetAttribute(fused_kernel,
                         cudaFuncAttributeMaxDynamicSharedMemorySize, SMEM_BYTES);

    ws2_kernel<<<CDIM, CDIM>>>(Ws);
    fused_kernel<<<NTOK / TPC, NTHR, SMEM_BYTES>>>(
        q, k, pos, mask, Ws, Wp1, bp1, Wp2, bp2,
        Wa1, ba1, Wa2, ba2, Wo, bo, out);
}